// round 2
// baseline (speedup 1.0000x reference)
#include <cuda_runtime.h>
#include <cuda_bf16.h>
#include <math.h>

// Problem constants
#define BB 64
#define SS 64
#define HH 1024
#define VV 32000
#define TT 13
#define SOS 2

// Output layout (concatenated returns): logp [B,T,V], h [1,B,H], c [1,B,H], attn [B,T,S]
#define OUT_LOGP 0
#define OUT_H    (BB*TT*VV)                 // 26,624,000
#define OUT_C    (OUT_H + BB*HH)            // 26,689,536
#define OUT_ATTN (OUT_C + BB*HH)            // 26,755,072
#define OUT_TOTAL (OUT_ATTN + BB*TT*SS)     // 26,808,320

// ---------------- scratch (device globals; no allocation allowed) ----------------
__device__ float g_keys[BB*SS*HH];     // 16 MB
__device__ float g_h[BB*HH];
__device__ float g_c[BB*HH];
__device__ float g_q[BB*HH];
__device__ float g_xi[BB*2*HH];        // [x | ctx]
__device__ float g_scores[BB*SS];
__device__ float g_w[BB*SS];
__device__ float g_gates[BB*4*HH];
__device__ float g_nh[BB*HH];
__device__ float g_logits[BB*VV];      // 8 MB

// ---------------- reductions ----------------
__device__ __forceinline__ float warpRedSum(float v) {
#pragma unroll
    for (int o = 16; o; o >>= 1) v += __shfl_xor_sync(0xffffffffu, v, o);
    return v;
}
__device__ __forceinline__ float warpRedMax(float v) {
#pragma unroll
    for (int o = 16; o; o >>= 1) v = fmaxf(v, __shfl_xor_sync(0xffffffffu, v, o));
    return v;
}
__device__ __forceinline__ float blockRedSum(float v, float* sm) {
    __syncthreads();
    v = warpRedSum(v);
    if ((threadIdx.x & 31) == 0) sm[threadIdx.x >> 5] = v;
    __syncthreads();
    if (threadIdx.x < 32) {
        float r = (threadIdx.x < (blockDim.x >> 5)) ? sm[threadIdx.x] : 0.f;
        r = warpRedSum(r);
        if (threadIdx.x == 0) sm[0] = r;
    }
    __syncthreads();
    return sm[0];
}
__device__ __forceinline__ float blockRedMax(float v, float* sm) {
    __syncthreads();
    v = warpRedMax(v);
    if ((threadIdx.x & 31) == 0) sm[threadIdx.x >> 5] = v;
    __syncthreads();
    if (threadIdx.x < 32) {
        float r = (threadIdx.x < (blockDim.x >> 5)) ? sm[threadIdx.x] : -1e30f;
        r = warpRedMax(r);
        if (threadIdx.x == 0) sm[0] = r;
    }
    __syncthreads();
    return sm[0];
}
__device__ __forceinline__ float sg(float x) { return 1.f / (1.f + expf(-x)); }

// ---------------- GEMM: C[M,N] = A[M,K] @ B[N,K]^T (+bias0+bias1) (+=C if accum) ----------------
// Tile: 64 (M) x 128 (N), K-chunk 16, 256 threads, 4x8 microtile.
// Requires: M%64==0, N%128==0, K%16==0, 16B-aligned pointers.
__global__ __launch_bounds__(256) void gemm_tn(
    const float* __restrict__ A, const float* __restrict__ B,
    const float* __restrict__ bias0, const float* __restrict__ bias1,
    float* __restrict__ C, int N, int K, int accum)
{
    __shared__ __align__(16) float As[16][64];
    __shared__ __align__(16) float Bs[16][128];
    const int tid = threadIdx.x;
    const int m0 = blockIdx.y * 64;
    const int n0 = blockIdx.x * 128;
    const int tm = (tid >> 4) << 2;        // 0..60
    const int tn = (tid & 15) << 3;        // 0..120
    const int ar = tid >> 2;               // 0..63
    const int ak = (tid & 3) << 2;         // 0,4,8,12
    const int br = tid >> 1;               // 0..127
    const int bk = (tid & 1) << 3;         // 0,8
    const float* Ap = A + (size_t)(m0 + ar) * K + ak;
    const float* Bp = B + (size_t)(n0 + br) * K + bk;

    float acc[4][8];
#pragma unroll
    for (int i = 0; i < 4; i++)
#pragma unroll
        for (int j = 0; j < 8; j++) acc[i][j] = 0.f;

    for (int k0 = 0; k0 < K; k0 += 16) {
        float4 av  = *(const float4*)(Ap + k0);
        float4 bv0 = *(const float4*)(Bp + k0);
        float4 bv1 = *(const float4*)(Bp + k0 + 4);
        __syncthreads();
        As[ak + 0][ar] = av.x;  As[ak + 1][ar] = av.y;
        As[ak + 2][ar] = av.z;  As[ak + 3][ar] = av.w;
        Bs[bk + 0][br] = bv0.x; Bs[bk + 1][br] = bv0.y;
        Bs[bk + 2][br] = bv0.z; Bs[bk + 3][br] = bv0.w;
        Bs[bk + 4][br] = bv1.x; Bs[bk + 5][br] = bv1.y;
        Bs[bk + 6][br] = bv1.z; Bs[bk + 7][br] = bv1.w;
        __syncthreads();
#pragma unroll
        for (int kk = 0; kk < 16; kk++) {
            float4 a  = *(const float4*)&As[kk][tm];
            float4 b0 = *(const float4*)&Bs[kk][tn];
            float4 b1 = *(const float4*)&Bs[kk][tn + 4];
            float aa[4] = {a.x, a.y, a.z, a.w};
            float bb[8] = {b0.x, b0.y, b0.z, b0.w, b1.x, b1.y, b1.z, b1.w};
#pragma unroll
            for (int i = 0; i < 4; i++)
#pragma unroll
                for (int j = 0; j < 8; j++)
                    acc[i][j] = fmaf(aa[i], bb[j], acc[i][j]);
        }
    }
#pragma unroll
    for (int i = 0; i < 4; i++) {
        float* Cp = C + (size_t)(m0 + tm + i) * N + n0 + tn;
#pragma unroll
        for (int j = 0; j < 8; j++) {
            float v = acc[i][j];
            int n = n0 + tn + j;
            if (bias0) v += bias0[n];
            if (bias1) v += bias1[n];
            if (accum) v += Cp[j];
            Cp[j] = v;
        }
    }
}

// ---------------- small kernels ----------------
__global__ void init_k(const float* __restrict__ h0, const float* __restrict__ c0) {
    int i = blockIdx.x * blockDim.x + threadIdx.x;
    g_h[i] = h0[i];
    g_c[i] = c0[i];
}

__global__ void embed_k(const float* __restrict__ emb, const int* __restrict__ tgt, int t) {
    int b = blockIdx.x;
    int tok = (t == 0) ? SOS : tgt[b * TT + (t - 1)];
    const float4* s = (const float4*)(emb + (size_t)tok * HH);
    float4* d = (float4*)(g_xi + b * 2 * HH);
    d[threadIdx.x] = s[threadIdx.x];   // 256 threads * 16B = 4KB row
}

// one block per (b,s): score = sum_h tanh(q[b,h]+keys[b,s,h]) * Va[h] + bv
__global__ __launch_bounds__(256) void scores_k(const float* __restrict__ Va,
                                                const float* __restrict__ bv) {
    int bs = blockIdx.x;
    int b = bs >> 6;
    int h4 = threadIdx.x * 4;
    float4 q  = *(const float4*)(g_q + b * HH + h4);
    float4 kp = *(const float4*)(g_keys + (size_t)bs * HH + h4);
    float4 va = *(const float4*)(Va + h4);
    float s = tanhf(q.x + kp.x) * va.x + tanhf(q.y + kp.y) * va.y +
              tanhf(q.z + kp.z) * va.z + tanhf(q.w + kp.w) * va.w;
    __shared__ float red[8];
    s = blockRedSum(s, red);
    if (threadIdx.x == 0) g_scores[bs] = s + bv[0];
}

// 32 threads per b, each handles s and s+32
__global__ void softmax_k(float* __restrict__ attn_out, int t) {
    int b = blockIdx.x;
    int s0 = threadIdx.x, s1 = s0 + 32;
    float v0 = g_scores[b * SS + s0];
    float v1 = g_scores[b * SS + s1];
    float m = warpRedMax(fmaxf(v0, v1));
    float e0 = expf(v0 - m), e1 = expf(v1 - m);
    float inv = 1.f / warpRedSum(e0 + e1);
    float w0 = e0 * inv, w1 = e1 * inv;
    g_w[b * SS + s0] = w0;
    g_w[b * SS + s1] = w1;
    if (attn_out) {
        attn_out[((size_t)b * TT + t) * SS + s0] = w0;
        attn_out[((size_t)b * TT + t) * SS + s1] = w1;
    }
}

// ctx[b,h] = sum_s w[b,s] * enc[b,s,h]; writes into xi[:, H:2H]
__global__ __launch_bounds__(256) void ctx_k(const float* __restrict__ enc) {
    int b = blockIdx.x;
    __shared__ float ws[SS];
    if (threadIdx.x < SS) ws[threadIdx.x] = g_w[b * SS + threadIdx.x];
    __syncthreads();
    float acc[4] = {0.f, 0.f, 0.f, 0.f};
    const float* eb = enc + (size_t)b * SS * HH;
#pragma unroll 4
    for (int s = 0; s < SS; s++) {
        float wv = ws[s];
        const float* er = eb + s * HH;
#pragma unroll
        for (int j = 0; j < 4; j++)
            acc[j] = fmaf(wv, er[threadIdx.x + j * 256], acc[j]);
    }
#pragma unroll
    for (int j = 0; j < 4; j++)
        g_xi[b * 2 * HH + HH + threadIdx.x + j * 256] = acc[j];
}

// LSTM cell update + layernorm. One block per b, 256 threads * 4 h each.
__global__ __launch_bounds__(256) void lstm_ln_k(const float* __restrict__ ln_g,
                                                 const float* __restrict__ ln_b) {
    int b = blockIdx.x;
    int h4 = threadIdx.x * 4;
    const float* g = g_gates + b * 4 * HH;
    float4 gi = *(const float4*)(g + h4);
    float4 gf = *(const float4*)(g + HH + h4);
    float4 gg = *(const float4*)(g + 2 * HH + h4);
    float4 go = *(const float4*)(g + 3 * HH + h4);
    float4 co = *(const float4*)(g_c + b * HH + h4);
    float cn[4], hn[4];
    cn[0] = sg(gf.x) * co.x + sg(gi.x) * tanhf(gg.x);
    cn[1] = sg(gf.y) * co.y + sg(gi.y) * tanhf(gg.y);
    cn[2] = sg(gf.z) * co.z + sg(gi.z) * tanhf(gg.z);
    cn[3] = sg(gf.w) * co.w + sg(gi.w) * tanhf(gg.w);
    hn[0] = sg(go.x) * tanhf(cn[0]);
    hn[1] = sg(go.y) * tanhf(cn[1]);
    hn[2] = sg(go.z) * tanhf(cn[2]);
    hn[3] = sg(go.w) * tanhf(cn[3]);
    float sum = hn[0] + hn[1] + hn[2] + hn[3];
    float sq  = hn[0]*hn[0] + hn[1]*hn[1] + hn[2]*hn[2] + hn[3]*hn[3];
    __shared__ float red[8];
    sum = blockRedSum(sum, red);
    sq  = blockRedSum(sq, red);
    float mu  = sum * (1.f / HH);
    float var = sq * (1.f / HH) - mu * mu;
    float inv = rsqrtf(var + 1e-5f);
    float4 gam = *(const float4*)(ln_g + h4);
    float4 bet = *(const float4*)(ln_b + h4);
    float4 nh;
    nh.x = (hn[0] - mu) * inv * gam.x + bet.x;
    nh.y = (hn[1] - mu) * inv * gam.y + bet.y;
    nh.z = (hn[2] - mu) * inv * gam.z + bet.z;
    nh.w = (hn[3] - mu) * inv * gam.w + bet.w;
    *(float4*)(g_c + b * HH + h4)  = make_float4(cn[0], cn[1], cn[2], cn[3]);
    *(float4*)(g_h + b * HH + h4)  = make_float4(hn[0], hn[1], hn[2], hn[3]);
    *(float4*)(g_nh + b * HH + h4) = nh;
}

__global__ __launch_bounds__(256) void logsoftmax_k(float* __restrict__ out, int t) {
    int b = blockIdx.x;
    const float* row = g_logits + (size_t)b * VV;
    __shared__ float red[8];
    float m = -1e30f;
    for (int i = threadIdx.x; i < VV; i += 256) m = fmaxf(m, row[i]);
    m = blockRedMax(m, red);
    float s = 0.f;
    for (int i = threadIdx.x; i < VV; i += 256) s += expf(row[i] - m);
    s = blockRedSum(s, red);
    float lse = m + logf(s);
    float* orow = out + ((size_t)b * TT + t) * VV;
    for (int i = threadIdx.x; i < VV; i += 256) orow[i] = row[i] - lse;
}

__global__ void writehc_k(float* __restrict__ out) {
    int i = blockIdx.x * blockDim.x + threadIdx.x;
    out[OUT_H + i] = g_h[i];
    out[OUT_C + i] = g_c[i];
}

// ---------------- launch ----------------
extern "C" void kernel_launch(void* const* d_in, const int* in_sizes, int n_in,
                              void* d_out, int out_size) {
    const float* enc   = (const float*)d_in[0];
    const float* enc_h = (const float*)d_in[1];
    const float* enc_c = (const float*)d_in[2];
    const int*   tgt   = (const int*)d_in[3];
    const float* emb   = (const float*)d_in[4];
    const float* Wa    = (const float*)d_in[5];
    const float* ba    = (const float*)d_in[6];
    const float* Ua    = (const float*)d_in[7];
    const float* bu    = (const float*)d_in[8];
    const float* Va    = (const float*)d_in[9];
    const float* bv    = (const float*)d_in[10];
    const float* W_ih  = (const float*)d_in[11];
    const float* W_hh  = (const float*)d_in[12];
    const float* b_ih  = (const float*)d_in[13];
    const float* b_hh  = (const float*)d_in[14];
    const float* ln_g  = (const float*)d_in[15];
    const float* ln_b  = (const float*)d_in[16];
    const float* outW  = (const float*)d_in[17];
    const float* outb  = (const float*)d_in[18];
    float* out = (float*)d_out;

    float *keys, *h, *q, *xi, *gates, *nh, *logits;
    cudaGetSymbolAddress((void**)&keys,   g_keys);
    cudaGetSymbolAddress((void**)&h,      g_h);
    cudaGetSymbolAddress((void**)&q,      g_q);
    cudaGetSymbolAddress((void**)&xi,     g_xi);
    cudaGetSymbolAddress((void**)&gates,  g_gates);
    cudaGetSymbolAddress((void**)&nh,     g_nh);
    cudaGetSymbolAddress((void**)&logits, g_logits);

    const bool full = (out_size >= OUT_TOTAL);
    float* attn_out = full ? (out + OUT_ATTN) : nullptr;

    init_k<<<BB * HH / 256, 256>>>(enc_h, enc_c);

    // keys_proj = enc @ Ua^T + bu : [4096,1024]x[1024,1024]
    gemm_tn<<<dim3(HH / 128, (BB * SS) / 64), 256>>>(enc, Ua, bu, nullptr, keys, HH, HH, 0);

    for (int t = 0; t < TT; t++) {
        embed_k<<<BB, 256>>>(emb, tgt, t);
        // q = h @ Wa^T + ba
        gemm_tn<<<dim3(HH / 128, 1), 256>>>(h, Wa, ba, nullptr, q, HH, HH, 0);
        scores_k<<<BB * SS, 256>>>(Va, bv);
        softmax_k<<<BB, 32>>>(attn_out, t);
        ctx_k<<<BB, 256>>>(enc);
        // gates = [x|ctx] @ W_ih^T + b_ih + b_hh ; then += h @ W_hh^T
        gemm_tn<<<dim3(4 * HH / 128, 1), 256>>>(xi, W_ih, b_ih, b_hh, gates, 4 * HH, 2 * HH, 0);
        gemm_tn<<<dim3(4 * HH / 128, 1), 256>>>(h, W_hh, nullptr, nullptr, gates, 4 * HH, HH, 1);
        lstm_ln_k<<<BB, 256>>>(ln_g, ln_b);
        // logits = nh @ outW^T + outb : [64,1024]x[1024,32000]
        gemm_tn<<<dim3(VV / 128, 1), 256>>>(nh, outW, outb, nullptr, logits, VV, HH, 0);
        logsoftmax_k<<<BB, 256>>>(out, t);
    }
    if (full) writehc_k<<<BB * HH / 256, 256>>>(out);
}

// round 7
// speedup vs baseline: 2.3832x; 2.3832x over previous
#include <cuda_runtime.h>
#include <cstdint>
#include <math.h>

#define BB 64
#define SS 64
#define HH 1024
#define VV 32000
#define TT 13
#define SOS 2

#define OUT_H    (BB*TT*VV)
#define OUT_C    (OUT_H + BB*HH)
#define OUT_ATTN (OUT_C + BB*HH)
#define OUT_TOTAL (OUT_ATTN + BB*TT*SS)

// ---------------- scratch (device globals) ----------------
__device__ float g_keys[BB*SS*HH];      // 16 MB  (fp32 keys_proj)
__device__ float g_enc_t[BB*SS*HH];     // 16 MB  (tf32-rounded enc)
__device__ float g_Ua_t[HH*HH];
__device__ float g_Wa_t[HH*HH];
__device__ float g_Wcat[4*HH*3*HH];     // 48 MB  [W_ih | W_hh] tf32-rounded
__device__ float g_outW_t[VV*HH];       // 128 MB tf32-rounded
__device__ float g_h[BB*HH];            // exact fp32 h (output)
__device__ float g_c[BB*HH];
__device__ float g_q[BB*HH];
__device__ float g_xi[BB*3*HH];         // [x | ctx | h]  (tf32-rounded)
__device__ float g_scores[BB*SS];
__device__ float g_w[BB*SS];
__device__ float g_gates[BB*4*HH];
__device__ float g_nh[BB*HH];           // tf32-rounded nh (logits GEMM input)
__device__ float g_logits[BB*VV];

// ---------------- helpers ----------------
__device__ __forceinline__ float tf32r(float x) {
    unsigned r;
    asm("cvt.rna.tf32.f32 %0, %1;" : "=r"(r) : "f"(x));
    return __uint_as_float(r);
}
__device__ __forceinline__ float warpRedSum(float v) {
#pragma unroll
    for (int o = 16; o; o >>= 1) v += __shfl_xor_sync(0xffffffffu, v, o);
    return v;
}
__device__ __forceinline__ float warpRedMax(float v) {
#pragma unroll
    for (int o = 16; o; o >>= 1) v = fmaxf(v, __shfl_xor_sync(0xffffffffu, v, o));
    return v;
}
__device__ __forceinline__ float blockRedSum(float v, float* sm) {
    __syncthreads();
    v = warpRedSum(v);
    if ((threadIdx.x & 31) == 0) sm[threadIdx.x >> 5] = v;
    __syncthreads();
    if (threadIdx.x < 32) {
        float r = (threadIdx.x < (blockDim.x >> 5)) ? sm[threadIdx.x] : 0.f;
        r = warpRedSum(r);
        if (threadIdx.x == 0) sm[0] = r;
    }
    __syncthreads();
    return sm[0];
}
__device__ __forceinline__ float blockRedMax(float v, float* sm) {
    __syncthreads();
    v = warpRedMax(v);
    if ((threadIdx.x & 31) == 0) sm[threadIdx.x >> 5] = v;
    __syncthreads();
    if (threadIdx.x < 32) {
        float r = (threadIdx.x < (blockDim.x >> 5)) ? sm[threadIdx.x] : -1e30f;
        r = warpRedMax(r);
        if (threadIdx.x == 0) sm[0] = r;
    }
    __syncthreads();
    return sm[0];
}
__device__ __forceinline__ float sg(float x) { return 1.f / (1.f + expf(-x)); }

__device__ __forceinline__ void cpa16(uint32_t dst, const float* src) {
    asm volatile("cp.async.cg.shared.global [%0], [%1], 16;" :: "r"(dst), "l"(src));
}
__device__ __forceinline__ void cpa_commit() {
    asm volatile("cp.async.commit_group;");
}
__device__ __forceinline__ void cpa_wait0() {
    asm volatile("cp.async.wait_group 0;");
}

// ---------------- tf32 tensor-core GEMM ----------------
// C[M,N] = A[M,K] @ B[N,K]^T (+bias0+bias1). A rows stride lda, B rows stride ldb.
// Block tile 64(M) x 128(N), BK=16, 256 threads (8 warps, 2m x 4n), double-buffered cp.async.
// Requires M%64==0, N%128==0, K%16==0. A/B already tf32-rounded (rna).
__global__ __launch_bounds__(256) void gemm_tf32(
    const float* __restrict__ A, int lda,
    const float* __restrict__ B, int ldb,
    const float* __restrict__ bias0, const float* __restrict__ bias1,
    float* __restrict__ C, int N, int K)
{
    __shared__ __align__(16) float As[2][64][20];
    __shared__ __align__(16) float Bs[2][128][20];

    const int tid  = threadIdx.x;
    const int lane = tid & 31;
    const int warp = tid >> 5;
    const int wm = (warp & 1) * 32;
    const int wn = (warp >> 1) * 32;
    const int m0 = blockIdx.y * 64;
    const int n0 = blockIdx.x * 128;
    const int lr = lane >> 2, lc = lane & 3;

    const int ldrow = tid >> 2;            // 0..63
    const int ldkk  = (tid & 3) * 4;       // 0,4,8,12
    const float* Ag  = A + (size_t)(m0 + ldrow) * lda + ldkk;
    const float* Bg0 = B + (size_t)(n0 + ldrow) * ldb + ldkk;
    const float* Bg1 = B + (size_t)(n0 + ldrow + 64) * ldb + ldkk;

    uint32_t sA[2], sB0[2], sB1[2];
#pragma unroll
    for (int bf = 0; bf < 2; bf++) {
        sA[bf]  = (uint32_t)__cvta_generic_to_shared(&As[bf][ldrow][ldkk]);
        sB0[bf] = (uint32_t)__cvta_generic_to_shared(&Bs[bf][ldrow][ldkk]);
        sB1[bf] = (uint32_t)__cvta_generic_to_shared(&Bs[bf][ldrow + 64][ldkk]);
    }

    float acc[2][4][4];
#pragma unroll
    for (int mt = 0; mt < 2; mt++)
#pragma unroll
        for (int nt = 0; nt < 4; nt++)
#pragma unroll
            for (int i = 0; i < 4; i++) acc[mt][nt][i] = 0.f;

    const int nk = K / 16;
    // prologue: chunk 0 -> buf 0
    cpa16(sA[0], Ag);
    cpa16(sB0[0], Bg0);
    cpa16(sB1[0], Bg1);
    cpa_commit();

    for (int it = 0; it < nk; it++) {
        cpa_wait0();
        __syncthreads();
        const int buf = it & 1;
        if (it + 1 < nk) {
            const int off = (it + 1) * 16;
            cpa16(sA[buf ^ 1], Ag + off);
            cpa16(sB0[buf ^ 1], Bg0 + off);
            cpa16(sB1[buf ^ 1], Bg1 + off);
        }
        cpa_commit();

#pragma unroll
        for (int ks = 0; ks < 16; ks += 8) {
            uint32_t a[2][4], b[4][2];
#pragma unroll
            for (int mt = 0; mt < 2; mt++) {
                const int r = wm + mt * 16 + lr;
                a[mt][0] = __float_as_uint(As[buf][r][ks + lc]);
                a[mt][1] = __float_as_uint(As[buf][r + 8][ks + lc]);
                a[mt][2] = __float_as_uint(As[buf][r][ks + lc + 4]);
                a[mt][3] = __float_as_uint(As[buf][r + 8][ks + lc + 4]);
            }
#pragma unroll
            for (int nt = 0; nt < 4; nt++) {
                const int r = wn + nt * 8 + lr;
                b[nt][0] = __float_as_uint(Bs[buf][r][ks + lc]);
                b[nt][1] = __float_as_uint(Bs[buf][r][ks + lc + 4]);
            }
#pragma unroll
            for (int mt = 0; mt < 2; mt++)
#pragma unroll
                for (int nt = 0; nt < 4; nt++) {
                    asm volatile(
                        "mma.sync.aligned.m16n8k8.row.col.f32.tf32.tf32.f32 "
                        "{%0,%1,%2,%3}, {%4,%5,%6,%7}, {%8,%9}, {%0,%1,%2,%3};"
                        : "+f"(acc[mt][nt][0]), "+f"(acc[mt][nt][1]),
                          "+f"(acc[mt][nt][2]), "+f"(acc[mt][nt][3])
                        : "r"(a[mt][0]), "r"(a[mt][1]), "r"(a[mt][2]), "r"(a[mt][3]),
                          "r"(b[nt][0]), "r"(b[nt][1]));
                }
        }
        __syncthreads();
    }

    // epilogue
#pragma unroll
    for (int mt = 0; mt < 2; mt++) {
        const int row = m0 + wm + mt * 16 + lr;
#pragma unroll
        for (int nt = 0; nt < 4; nt++) {
            const int col = n0 + wn + nt * 8 + 2 * lc;
            float b0a = bias0 ? bias0[col] : 0.f;
            float b0b = bias0 ? bias0[col + 1] : 0.f;
            if (bias1) { b0a += bias1[col]; b0b += bias1[col + 1]; }
            C[(size_t)row * N + col]           = acc[mt][nt][0] + b0a;
            C[(size_t)row * N + col + 1]       = acc[mt][nt][1] + b0b;
            C[(size_t)(row + 8) * N + col]     = acc[mt][nt][2] + b0a;
            C[(size_t)(row + 8) * N + col + 1] = acc[mt][nt][3] + b0b;
        }
    }
}

// ---------------- prep kernels ----------------
__global__ void cvt_k(const float* __restrict__ src, float* __restrict__ dst, int n4) {
    int i = blockIdx.x * blockDim.x + threadIdx.x;
    if (i < n4) {
        float4 v = ((const float4*)src)[i];
        v.x = tf32r(v.x); v.y = tf32r(v.y); v.z = tf32r(v.z); v.w = tf32r(v.w);
        ((float4*)dst)[i] = v;
    }
}

// Wcat[r][0:2H] = W_ih[r], Wcat[r][2H:3H] = W_hh[r]   (tf32-rounded)
__global__ void wcat_k(const float* __restrict__ W_ih, const float* __restrict__ W_hh) {
    int i = blockIdx.x * blockDim.x + threadIdx.x;   // float4 index over 4096*3072/4
    const int row = i / (3 * HH / 4);
    const int c4  = i % (3 * HH / 4);
    const float4* src = (c4 < 2 * HH / 4)
        ? ((const float4*)(W_ih + (size_t)row * 2 * HH)) + c4
        : ((const float4*)(W_hh + (size_t)row * HH)) + (c4 - 2 * HH / 4);
    float4 v = *src;
    v.x = tf32r(v.x); v.y = tf32r(v.y); v.z = tf32r(v.z); v.w = tf32r(v.w);
    ((float4*)g_Wcat)[i] = v;
}

__global__ void init_k(const float* __restrict__ h0, const float* __restrict__ c0) {
    int i = blockIdx.x * blockDim.x + threadIdx.x;
    g_h[i] = h0[i];
    g_c[i] = c0[i];
    int b = i / HH, hh = i - b * HH;
    g_xi[b * 3 * HH + 2 * HH + hh] = tf32r(h0[i]);
}

// ---------------- per-step kernels ----------------
__global__ void embed_k(const float* __restrict__ emb, const int* __restrict__ tgt, int t) {
    int b = blockIdx.x;
    int tok = (t == 0) ? SOS : tgt[b * TT + (t - 1)];
    float4 v = ((const float4*)(emb + (size_t)tok * HH))[threadIdx.x];
    v.x = tf32r(v.x); v.y = tf32r(v.y); v.z = tf32r(v.z); v.w = tf32r(v.w);
    ((float4*)(g_xi + (size_t)b * 3 * HH))[threadIdx.x] = v;
}

__global__ __launch_bounds__(256) void scores_k(const float* __restrict__ Va,
                                                const float* __restrict__ bv) {
    int bs = blockIdx.x;
    int b = bs >> 6;
    int h4 = threadIdx.x * 4;
    float4 q  = *(const float4*)(g_q + b * HH + h4);
    float4 kp = *(const float4*)(g_keys + (size_t)bs * HH + h4);
    float4 va = *(const float4*)(Va + h4);
    float s = tanhf(q.x + kp.x) * va.x + tanhf(q.y + kp.y) * va.y +
              tanhf(q.z + kp.z) * va.z + tanhf(q.w + kp.w) * va.w;
    __shared__ float red[8];
    s = blockRedSum(s, red);
    if (threadIdx.x == 0) g_scores[bs] = s + bv[0];
}

__global__ void softmax_k(float* __restrict__ attn_out, int t) {
    int b = blockIdx.x;
    int s0 = threadIdx.x, s1 = s0 + 32;
    float v0 = g_scores[b * SS + s0];
    float v1 = g_scores[b * SS + s1];
    float m = warpRedMax(fmaxf(v0, v1));
    float e0 = expf(v0 - m), e1 = expf(v1 - m);
    float inv = 1.f / warpRedSum(e0 + e1);
    float w0 = e0 * inv, w1 = e1 * inv;
    g_w[b * SS + s0] = w0;
    g_w[b * SS + s1] = w1;
    if (attn_out) {
        attn_out[((size_t)b * TT + t) * SS + s0] = w0;
        attn_out[((size_t)b * TT + t) * SS + s1] = w1;
    }
}

__global__ __launch_bounds__(256) void ctx_k(const float* __restrict__ enc) {
    int b = blockIdx.x;
    __shared__ float ws[SS];
    if (threadIdx.x < SS) ws[threadIdx.x] = g_w[b * SS + threadIdx.x];
    __syncthreads();
    float acc[4] = {0.f, 0.f, 0.f, 0.f};
    const float* eb = enc + (size_t)b * SS * HH;
#pragma unroll 4
    for (int s = 0; s < SS; s++) {
        float wv = ws[s];
        const float* er = eb + s * HH;
#pragma unroll
        for (int j = 0; j < 4; j++)
            acc[j] = fmaf(wv, er[threadIdx.x + j * 256], acc[j]);
    }
#pragma unroll
    for (int j = 0; j < 4; j++)
        g_xi[b * 3 * HH + HH + threadIdx.x + j * 256] = tf32r(acc[j]);
}

__global__ __launch_bounds__(256) void lstm_ln_k(const float* __restrict__ ln_g,
                                                 const float* __restrict__ ln_b) {
    int b = blockIdx.x;
    int h4 = threadIdx.x * 4;
    const float* g = g_gates + b * 4 * HH;
    float4 gi = *(const float4*)(g + h4);
    float4 gf = *(const float4*)(g + HH + h4);
    float4 gg = *(const float4*)(g + 2 * HH + h4);
    float4 go = *(const float4*)(g + 3 * HH + h4);
    float4 co = *(const float4*)(g_c + b * HH + h4);
    float cn[4], hn[4];
    cn[0] = sg(gf.x) * co.x + sg(gi.x) * tanhf(gg.x);
    cn[1] = sg(gf.y) * co.y + sg(gi.y) * tanhf(gg.y);
    cn[2] = sg(gf.z) * co.z + sg(gi.z) * tanhf(gg.z);
    cn[3] = sg(gf.w) * co.w + sg(gi.w) * tanhf(gg.w);
    hn[0] = sg(go.x) * tanhf(cn[0]);
    hn[1] = sg(go.y) * tanhf(cn[1]);
    hn[2] = sg(go.z) * tanhf(cn[2]);
    hn[3] = sg(go.w) * tanhf(cn[3]);
    float sum = hn[0] + hn[1] + hn[2] + hn[3];
    float sq  = hn[0]*hn[0] + hn[1]*hn[1] + hn[2]*hn[2] + hn[3]*hn[3];
    __shared__ float red[8];
    sum = blockRedSum(sum, red);
    sq  = blockRedSum(sq, red);
    float mu  = sum * (1.f / HH);
    float var = sq * (1.f / HH) - mu * mu;
    float inv = rsqrtf(var + 1e-5f);
    float4 gam = *(const float4*)(ln_g + h4);
    float4 bet = *(const float4*)(ln_b + h4);
    float nh0 = (hn[0] - mu) * inv * gam.x + bet.x;
    float nh1 = (hn[1] - mu) * inv * gam.y + bet.y;
    float nh2 = (hn[2] - mu) * inv * gam.z + bet.z;
    float nh3 = (hn[3] - mu) * inv * gam.w + bet.w;
    *(float4*)(g_c + b * HH + h4) = make_float4(cn[0], cn[1], cn[2], cn[3]);
    *(float4*)(g_h + b * HH + h4) = make_float4(hn[0], hn[1], hn[2], hn[3]);
    // tf32-rounded copies for the tensor-core GEMMs
    *(float4*)(g_nh + b * HH + h4) =
        make_float4(tf32r(nh0), tf32r(nh1), tf32r(nh2), tf32r(nh3));
    *(float4*)(g_xi + b * 3 * HH + 2 * HH + h4) =
        make_float4(tf32r(hn[0]), tf32r(hn[1]), tf32r(hn[2]), tf32r(hn[3]));
}

__global__ __launch_bounds__(256) void logsoftmax_k(float* __restrict__ out, int t) {
    int b = blockIdx.x;
    const float* row = g_logits + (size_t)b * VV;
    __shared__ float red[8];
    float m = -1e30f;
    for (int i = threadIdx.x; i < VV; i += 256) m = fmaxf(m, row[i]);
    m = blockRedMax(m, red);
    float s = 0.f;
    for (int i = threadIdx.x; i < VV; i += 256) s += expf(row[i] - m);
    s = blockRedSum(s, red);
    float lse = m + logf(s);
    float* orow = out + ((size_t)b * TT + t) * VV;
    for (int i = threadIdx.x; i < VV; i += 256) orow[i] = row[i] - lse;
}

__global__ void writehc_k(float* __restrict__ out) {
    int i = blockIdx.x * blockDim.x + threadIdx.x;
    out[OUT_H + i] = g_h[i];
    out[OUT_C + i] = g_c[i];
}

// ---------------- launch ----------------
extern "C" void kernel_launch(void* const* d_in, const int* in_sizes, int n_in,
                              void* d_out, int out_size) {
    const float* enc   = (const float*)d_in[0];
    const float* enc_h = (const float*)d_in[1];
    const float* enc_c = (const float*)d_in[2];
    const int*   tgt   = (const int*)d_in[3];
    const float* emb   = (const float*)d_in[4];
    const float* Wa    = (const float*)d_in[5];
    const float* ba    = (const float*)d_in[6];
    const float* Ua    = (const float*)d_in[7];
    const float* bu    = (const float*)d_in[8];
    const float* Va    = (const float*)d_in[9];
    const float* bv    = (const float*)d_in[10];
    const float* W_ih  = (const float*)d_in[11];
    const float* W_hh  = (const float*)d_in[12];
    const float* b_ih  = (const float*)d_in[13];
    const float* b_hh  = (const float*)d_in[14];
    const float* ln_g  = (const float*)d_in[15];
    const float* ln_b  = (const float*)d_in[16];
    const float* outW  = (const float*)d_in[17];
    const float* outb  = (const float*)d_in[18];
    float* out = (float*)d_out;

    float *keys, *enc_t, *Ua_t, *Wa_t, *Wcat, *outW_t, *q, *xi, *gates, *nh, *logits;
    cudaGetSymbolAddress((void**)&keys,   g_keys);
    cudaGetSymbolAddress((void**)&enc_t,  g_enc_t);
    cudaGetSymbolAddress((void**)&Ua_t,   g_Ua_t);
    cudaGetSymbolAddress((void**)&Wa_t,   g_Wa_t);
    cudaGetSymbolAddress((void**)&Wcat,   g_Wcat);
    cudaGetSymbolAddress((void**)&outW_t, g_outW_t);
    cudaGetSymbolAddress((void**)&q,      g_q);
    cudaGetSymbolAddress((void**)&xi,     g_xi);
    cudaGetSymbolAddress((void**)&gates,  g_gates);
    cudaGetSymbolAddress((void**)&nh,     g_nh);
    cudaGetSymbolAddress((void**)&logits, g_logits);

    const bool full = (out_size >= OUT_TOTAL);
    float* attn_out = full ? (out + OUT_ATTN) : nullptr;

    // one-time prep: tf32-round all GEMM operands
    cvt_k<<<(BB*SS*HH/4 + 255)/256, 256>>>(enc, enc_t, BB*SS*HH/4);
    cvt_k<<<(HH*HH/4 + 255)/256, 256>>>(Ua, Ua_t, HH*HH/4);
    cvt_k<<<(HH*HH/4 + 255)/256, 256>>>(Wa, Wa_t, HH*HH/4);
    cvt_k<<<(VV*HH/4 + 255)/256, 256>>>(outW, outW_t, VV*HH/4);
    wcat_k<<<(4*HH*3*HH/4)/256, 256>>>(W_ih, W_hh);
    init_k<<<BB*HH/256, 256>>>(enc_h, enc_c);

    // keys_proj = enc @ Ua^T + bu : [4096,1024]x[1024,1024]
    gemm_tf32<<<dim3(HH/128, BB*SS/64), 256>>>(enc_t, HH, Ua_t, HH, bu, nullptr,
                                               keys, HH, HH);

    for (int t = 0; t < TT; t++) {
        embed_k<<<BB, 256>>>(emb, tgt, t);
        // q = h @ Wa^T + ba  (h slice of xi, lda = 3H)
        gemm_tf32<<<dim3(HH/128, 1), 256>>>(xi + 2*HH, 3*HH, Wa_t, HH, ba, nullptr,
                                            q, HH, HH);
        scores_k<<<BB*SS, 256>>>(Va, bv);
        softmax_k<<<BB, 32>>>(attn_out, t);
        ctx_k<<<BB, 256>>>(enc);
        // gates = [x|ctx|h] @ Wcat^T + b_ih + b_hh
        gemm_tf32<<<dim3(4*HH/128, 1), 256>>>(xi, 3*HH, Wcat, 3*HH, b_ih, b_hh,
                                              gates, 4*HH, 3*HH);
        lstm_ln_k<<<BB, 256>>>(ln_g, ln_b);
        // logits = nh @ outW^T + outb
        gemm_tf32<<<dim3(VV/128, 1), 256>>>(nh, HH, outW_t, HH, outb, nullptr,
                                            logits, VV, HH);
        logsoftmax_k<<<BB, 256>>>(out, t);
    }
    if (full) writehc_k<<<BB*HH/256, 256>>>(out);
}

// round 15
// speedup vs baseline: 3.3721x; 1.4149x over previous
#include <cuda_runtime.h>
#include <cstdint>
#include <math.h>

#define BB 64
#define SS 64
#define HH 1024
#define VV 32000
#define TT 13
#define SOS 2

#define OUT_H    (BB*TT*VV)
#define OUT_C    (OUT_H + BB*HH)
#define OUT_ATTN (OUT_C + BB*HH)
#define OUT_TOTAL (OUT_ATTN + BB*TT*SS)

// ---------------- scratch (device globals) ----------------
__device__ float g_keys[BB*SS*HH];      // 16 MB  (fp32 keys_proj)
__device__ float g_enc_t[BB*SS*HH];     // 16 MB  (tf32-rounded enc)
__device__ float g_Ua_t[HH*HH];
__device__ float g_Wa_t[HH*HH];
__device__ float g_Wcat[4*HH*3*HH];     // 48 MB  [W_ih | W_hh] tf32-rounded
__device__ float g_outW_t[VV*HH];       // 128 MB tf32-rounded
__device__ float g_h[BB*HH];
__device__ float g_c[BB*HH];
__device__ float g_q[BB*HH];
__device__ float g_xi[BB*3*HH];         // [x | ctx | h]  (tf32-rounded)
__device__ float g_scores[BB*SS];
__device__ float g_gates[BB*4*HH];
__device__ float g_nh[BB*HH];
__device__ float g_logits[BB*VV];

// ---------------- helpers ----------------
__device__ __forceinline__ float tf32r(float x) {
    unsigned r;
    asm("cvt.rna.tf32.f32 %0, %1;" : "=r"(r) : "f"(x));
    return __uint_as_float(r);
}
__device__ __forceinline__ float tanh_fast(float x) {
    float y;
    asm("tanh.approx.f32 %0, %1;" : "=f"(y) : "f"(x));
    return y;
}
__device__ __forceinline__ float warpRedSum(float v) {
#pragma unroll
    for (int o = 16; o; o >>= 1) v += __shfl_xor_sync(0xffffffffu, v, o);
    return v;
}
__device__ __forceinline__ float warpRedMax(float v) {
#pragma unroll
    for (int o = 16; o; o >>= 1) v = fmaxf(v, __shfl_xor_sync(0xffffffffu, v, o));
    return v;
}
__device__ __forceinline__ float blockRedSum(float v, float* sm) {
    __syncthreads();
    v = warpRedSum(v);
    if ((threadIdx.x & 31) == 0) sm[threadIdx.x >> 5] = v;
    __syncthreads();
    if (threadIdx.x < 32) {
        float r = (threadIdx.x < (blockDim.x >> 5)) ? sm[threadIdx.x] : 0.f;
        r = warpRedSum(r);
        if (threadIdx.x == 0) sm[0] = r;
    }
    __syncthreads();
    return sm[0];
}
__device__ __forceinline__ float blockRedMax(float v, float* sm) {
    __syncthreads();
    v = warpRedMax(v);
    if ((threadIdx.x & 31) == 0) sm[threadIdx.x >> 5] = v;
    __syncthreads();
    if (threadIdx.x < 32) {
        float r = (threadIdx.x < (blockDim.x >> 5)) ? sm[threadIdx.x] : -1e30f;
        r = warpRedMax(r);
        if (threadIdx.x == 0) sm[0] = r;
    }
    __syncthreads();
    return sm[0];
}
__device__ __forceinline__ float sg(float x) { return 1.f / (1.f + __expf(-x)); }

__device__ __forceinline__ void cpa16(uint32_t dst, const float* src) {
    asm volatile("cp.async.cg.shared.global [%0], [%1], 16;" :: "r"(dst), "l"(src));
}
__device__ __forceinline__ void cpa_commit() {
    asm volatile("cp.async.commit_group;");
}

// ---------------- tf32 tensor-core GEMM, 3-stage cp.async pipeline ----------------
// C[M,N] = A[M,K] @ B[N,K]^T (+bias0+bias1). Requires M%64==0, N%128==0, K%16==0.
#define STG 3
__global__ __launch_bounds__(256) void gemm_tf32(
    const float* __restrict__ A, int lda,
    const float* __restrict__ B, int ldb,
    const float* __restrict__ bias0, const float* __restrict__ bias1,
    float* __restrict__ C, int N, int K)
{
    __shared__ __align__(16) float As[STG][64][20];
    __shared__ __align__(16) float Bs[STG][128][20];

    const int tid  = threadIdx.x;
    const int lane = tid & 31;
    const int warp = tid >> 5;
    const int wm = (warp & 1) * 32;
    const int wn = (warp >> 1) * 32;
    const int m0 = blockIdx.y * 64;
    const int n0 = blockIdx.x * 128;
    const int lr = lane >> 2, lc = lane & 3;

    const int ldrow = tid >> 2;            // 0..63
    const int ldkk  = (tid & 3) * 4;       // 0,4,8,12
    const float* Ag  = A + (size_t)(m0 + ldrow) * lda + ldkk;
    const float* Bg0 = B + (size_t)(n0 + ldrow) * ldb + ldkk;
    const float* Bg1 = B + (size_t)(n0 + ldrow + 64) * ldb + ldkk;

    uint32_t sA[STG], sB0[STG], sB1[STG];
#pragma unroll
    for (int bf = 0; bf < STG; bf++) {
        sA[bf]  = (uint32_t)__cvta_generic_to_shared(&As[bf][ldrow][ldkk]);
        sB0[bf] = (uint32_t)__cvta_generic_to_shared(&Bs[bf][ldrow][ldkk]);
        sB1[bf] = (uint32_t)__cvta_generic_to_shared(&Bs[bf][ldrow + 64][ldkk]);
    }

    float acc[2][4][4];
#pragma unroll
    for (int mt = 0; mt < 2; mt++)
#pragma unroll
        for (int nt = 0; nt < 4; nt++)
#pragma unroll
            for (int i = 0; i < 4; i++) acc[mt][nt][i] = 0.f;

    const int nk = K / 16;
    // prologue: chunks 0..STG-2
#pragma unroll
    for (int s = 0; s < STG - 1; s++) {
        if (s < nk) {
            const int off = s * 16;
            cpa16(sA[s],  Ag  + off);
            cpa16(sB0[s], Bg0 + off);
            cpa16(sB1[s], Bg1 + off);
        }
        cpa_commit();
    }

    for (int it = 0; it < nk; it++) {
        asm volatile("cp.async.wait_group %0;" :: "n"(STG - 2));
        __syncthreads();
        const int c = it + STG - 1;
        if (c < nk) {
            const int lbuf = c % STG;
            const int off = c * 16;
            cpa16(sA[lbuf],  Ag  + off);
            cpa16(sB0[lbuf], Bg0 + off);
            cpa16(sB1[lbuf], Bg1 + off);
        }
        cpa_commit();

        const int buf = it % STG;
#pragma unroll
        for (int ks = 0; ks < 16; ks += 8) {
            uint32_t a[2][4], b[4][2];
#pragma unroll
            for (int mt = 0; mt < 2; mt++) {
                const int r = wm + mt * 16 + lr;
                a[mt][0] = __float_as_uint(As[buf][r][ks + lc]);
                a[mt][1] = __float_as_uint(As[buf][r + 8][ks + lc]);
                a[mt][2] = __float_as_uint(As[buf][r][ks + lc + 4]);
                a[mt][3] = __float_as_uint(As[buf][r + 8][ks + lc + 4]);
            }
#pragma unroll
            for (int nt = 0; nt < 4; nt++) {
                const int r = wn + nt * 8 + lr;
                b[nt][0] = __float_as_uint(Bs[buf][r][ks + lc]);
                b[nt][1] = __float_as_uint(Bs[buf][r][ks + lc + 4]);
            }
#pragma unroll
            for (int mt = 0; mt < 2; mt++)
#pragma unroll
                for (int nt = 0; nt < 4; nt++) {
                    asm volatile(
                        "mma.sync.aligned.m16n8k8.row.col.f32.tf32.tf32.f32 "
                        "{%0,%1,%2,%3}, {%4,%5,%6,%7}, {%8,%9}, {%0,%1,%2,%3};"
                        : "+f"(acc[mt][nt][0]), "+f"(acc[mt][nt][1]),
                          "+f"(acc[mt][nt][2]), "+f"(acc[mt][nt][3])
                        : "r"(a[mt][0]), "r"(a[mt][1]), "r"(a[mt][2]), "r"(a[mt][3]),
                          "r"(b[nt][0]), "r"(b[nt][1]));
                }
        }
        __syncthreads();
    }

#pragma unroll
    for (int mt = 0; mt < 2; mt++) {
        const int row = m0 + wm + mt * 16 + lr;
#pragma unroll
        for (int nt = 0; nt < 4; nt++) {
            const int col = n0 + wn + nt * 8 + 2 * lc;
            float b0a = bias0 ? bias0[col] : 0.f;
            float b0b = bias0 ? bias0[col + 1] : 0.f;
            if (bias1) { b0a += bias1[col]; b0b += bias1[col + 1]; }
            C[(size_t)row * N + col]           = acc[mt][nt][0] + b0a;
            C[(size_t)row * N + col + 1]       = acc[mt][nt][1] + b0b;
            C[(size_t)(row + 8) * N + col]     = acc[mt][nt][2] + b0a;
            C[(size_t)(row + 8) * N + col + 1] = acc[mt][nt][3] + b0b;
        }
    }
}

// ---------------- prep kernels ----------------
__global__ void cvt_k(const float* __restrict__ src, float* __restrict__ dst, int n4) {
    int i = blockIdx.x * blockDim.x + threadIdx.x;
    if (i < n4) {
        float4 v = ((const float4*)src)[i];
        v.x = tf32r(v.x); v.y = tf32r(v.y); v.z = tf32r(v.z); v.w = tf32r(v.w);
        ((float4*)dst)[i] = v;
    }
}

__global__ void wcat_k(const float* __restrict__ W_ih, const float* __restrict__ W_hh) {
    int i = blockIdx.x * blockDim.x + threadIdx.x;
    const int row = i / (3 * HH / 4);
    const int c4  = i % (3 * HH / 4);
    const float4* src = (c4 < 2 * HH / 4)
        ? ((const float4*)(W_ih + (size_t)row * 2 * HH)) + c4
        : ((const float4*)(W_hh + (size_t)row * HH)) + (c4 - 2 * HH / 4);
    float4 v = *src;
    v.x = tf32r(v.x); v.y = tf32r(v.y); v.z = tf32r(v.z); v.w = tf32r(v.w);
    ((float4*)g_Wcat)[i] = v;
}

__global__ void init_k(const float* __restrict__ h0, const float* __restrict__ c0) {
    int i = blockIdx.x * blockDim.x + threadIdx.x;
    g_h[i] = h0[i];
    g_c[i] = c0[i];
    int b = i / HH, hh = i - b * HH;
    g_xi[b * 3 * HH + 2 * HH + hh] = tf32r(h0[i]);
}

// ---------------- per-step kernels ----------------
// one block per (b,s): score = sum_h tanh(q+keys) * Va + bv   (tanh.approx)
__global__ __launch_bounds__(256) void scores_k(const float* __restrict__ Va,
                                                const float* __restrict__ bv) {
    int bs = blockIdx.x;
    int b = bs >> 6;
    int h4 = threadIdx.x * 4;
    float4 q  = *(const float4*)(g_q + b * HH + h4);
    float4 kp = *(const float4*)(g_keys + (size_t)bs * HH + h4);
    float4 va = *(const float4*)(Va + h4);
    float s = tanh_fast(q.x + kp.x) * va.x + tanh_fast(q.y + kp.y) * va.y +
              tanh_fast(q.z + kp.z) * va.z + tanh_fast(q.w + kp.w) * va.w;
    __shared__ float red[8];
    s = blockRedSum(s, red);
    if (threadIdx.x == 0) g_scores[bs] = s + bv[0];
}

// fused: softmax(scores) + attn write + ctx + embed.  grid (B, 4), 256 threads.
__global__ __launch_bounds__(256) void ctx_fused_k(
    const float* __restrict__ enc, const float* __restrict__ emb,
    const int* __restrict__ tgt, float* __restrict__ attn_out, int t)
{
    const int b = blockIdx.x;
    const int seg = blockIdx.y;              // 0..3, 256 h-cols each
    const int tid = threadIdx.x;
    __shared__ float ws[SS];

    if (tid < 32) {
        float v0 = g_scores[b * SS + tid];
        float v1 = g_scores[b * SS + tid + 32];
        float m = warpRedMax(fmaxf(v0, v1));
        float e0 = __expf(v0 - m), e1 = __expf(v1 - m);
        float inv = 1.f / warpRedSum(e0 + e1);
        float w0 = e0 * inv, w1 = e1 * inv;
        ws[tid] = w0;
        ws[tid + 32] = w1;
        if (seg == 0 && attn_out) {
            attn_out[((size_t)b * TT + t) * SS + tid] = w0;
            attn_out[((size_t)b * TT + t) * SS + tid + 32] = w1;
        }
    }
    __syncthreads();

    const int h = seg * 256 + tid;
    const float* eb = enc + (size_t)b * SS * HH + h;
    float acc = 0.f;
#pragma unroll 8
    for (int s = 0; s < SS; s++)
        acc = fmaf(ws[s], eb[s * HH], acc);
    g_xi[b * 3 * HH + HH + h] = tf32r(acc);

    // embed (teacher forcing input for this step)
    int tok = (t == 0) ? SOS : tgt[b * TT + (t - 1)];
    g_xi[b * 3 * HH + h] = tf32r(emb[(size_t)tok * HH + h]);
}

__global__ __launch_bounds__(256) void lstm_ln_k(const float* __restrict__ ln_g,
                                                 const float* __restrict__ ln_b) {
    int b = blockIdx.x;
    int h4 = threadIdx.x * 4;
    const float* g = g_gates + b * 4 * HH;
    float4 gi = *(const float4*)(g + h4);
    float4 gf = *(const float4*)(g + HH + h4);
    float4 gg = *(const float4*)(g + 2 * HH + h4);
    float4 go = *(const float4*)(g + 3 * HH + h4);
    float4 co = *(const float4*)(g_c + b * HH + h4);
    float cn[4], hn[4];
    cn[0] = sg(gf.x) * co.x + sg(gi.x) * tanhf(gg.x);
    cn[1] = sg(gf.y) * co.y + sg(gi.y) * tanhf(gg.y);
    cn[2] = sg(gf.z) * co.z + sg(gi.z) * tanhf(gg.z);
    cn[3] = sg(gf.w) * co.w + sg(gi.w) * tanhf(gg.w);
    hn[0] = sg(go.x) * tanhf(cn[0]);
    hn[1] = sg(go.y) * tanhf(cn[1]);
    hn[2] = sg(go.z) * tanhf(cn[2]);
    hn[3] = sg(go.w) * tanhf(cn[3]);
    float sum = hn[0] + hn[1] + hn[2] + hn[3];
    float sq  = hn[0]*hn[0] + hn[1]*hn[1] + hn[2]*hn[2] + hn[3]*hn[3];
    __shared__ float red[8];
    sum = blockRedSum(sum, red);
    sq  = blockRedSum(sq, red);
    float mu  = sum * (1.f / HH);
    float var = sq * (1.f / HH) - mu * mu;
    float inv = rsqrtf(var + 1e-5f);
    float4 gam = *(const float4*)(ln_g + h4);
    float4 bet = *(const float4*)(ln_b + h4);
    float nh0 = (hn[0] - mu) * inv * gam.x + bet.x;
    float nh1 = (hn[1] - mu) * inv * gam.y + bet.y;
    float nh2 = (hn[2] - mu) * inv * gam.z + bet.z;
    float nh3 = (hn[3] - mu) * inv * gam.w + bet.w;
    *(float4*)(g_c + b * HH + h4) = make_float4(cn[0], cn[1], cn[2], cn[3]);
    *(float4*)(g_h + b * HH + h4) = make_float4(hn[0], hn[1], hn[2], hn[3]);
    *(float4*)(g_nh + b * HH + h4) =
        make_float4(tf32r(nh0), tf32r(nh1), tf32r(nh2), tf32r(nh3));
    *(float4*)(g_xi + b * 3 * HH + 2 * HH + h4) =
        make_float4(tf32r(hn[0]), tf32r(hn[1]), tf32r(hn[2]), tf32r(hn[3]));
}

__global__ __launch_bounds__(512) void logsoftmax_k(float* __restrict__ out, int t) {
    int b = blockIdx.x;
    const float4* row4 = (const float4*)(g_logits + (size_t)b * VV);
    __shared__ float red[16];
    const int n4 = VV / 4;   // 8000
    float m = -1e30f;
    for (int i = threadIdx.x; i < n4; i += 512) {
        float4 v = row4[i];
        m = fmaxf(m, fmaxf(fmaxf(v.x, v.y), fmaxf(v.z, v.w)));
    }
    m = blockRedMax(m, red);
    float s = 0.f;
    for (int i = threadIdx.x; i < n4; i += 512) {
        float4 v = row4[i];
        s += __expf(v.x - m) + __expf(v.y - m) + __expf(v.z - m) + __expf(v.w - m);
    }
    s = blockRedSum(s, red);
    float lse = m + logf(s);
    float4* orow = (float4*)(out + ((size_t)b * TT + t) * VV);
    for (int i = threadIdx.x; i < n4; i += 512) {
        float4 v = row4[i];
        v.x -= lse; v.y -= lse; v.z -= lse; v.w -= lse;
        orow[i] = v;
    }
}

__global__ void writehc_k(float* __restrict__ out) {
    int i = blockIdx.x * blockDim.x + threadIdx.x;
    out[OUT_H + i] = g_h[i];
    out[OUT_C + i] = g_c[i];
}

// ---------------- launch ----------------
extern "C" void kernel_launch(void* const* d_in, const int* in_sizes, int n_in,
                              void* d_out, int out_size) {
    const float* enc   = (const float*)d_in[0];
    const float* enc_h = (const float*)d_in[1];
    const float* enc_c = (const float*)d_in[2];
    const int*   tgt   = (const int*)d_in[3];
    const float* emb   = (const float*)d_in[4];
    const float* Wa    = (const float*)d_in[5];
    const float* ba    = (const float*)d_in[6];
    const float* Ua    = (const float*)d_in[7];
    const float* bu    = (const float*)d_in[8];
    const float* Va    = (const float*)d_in[9];
    const float* bv    = (const float*)d_in[10];
    const float* W_ih  = (const float*)d_in[11];
    const float* W_hh  = (const float*)d_in[12];
    const float* b_ih  = (const float*)d_in[13];
    const float* b_hh  = (const float*)d_in[14];
    const float* ln_g  = (const float*)d_in[15];
    const float* ln_b  = (const float*)d_in[16];
    const float* outW  = (const float*)d_in[17];
    const float* outb  = (const float*)d_in[18];
    float* out = (float*)d_out;

    float *keys, *enc_t, *Ua_t, *Wa_t, *Wcat, *outW_t, *q, *xi, *gates, *nh, *logits;
    cudaGetSymbolAddress((void**)&keys,   g_keys);
    cudaGetSymbolAddress((void**)&enc_t,  g_enc_t);
    cudaGetSymbolAddress((void**)&Ua_t,   g_Ua_t);
    cudaGetSymbolAddress((void**)&Wa_t,   g_Wa_t);
    cudaGetSymbolAddress((void**)&Wcat,   g_Wcat);
    cudaGetSymbolAddress((void**)&outW_t, g_outW_t);
    cudaGetSymbolAddress((void**)&q,      g_q);
    cudaGetSymbolAddress((void**)&xi,     g_xi);
    cudaGetSymbolAddress((void**)&gates,  g_gates);
    cudaGetSymbolAddress((void**)&nh,     g_nh);
    cudaGetSymbolAddress((void**)&logits, g_logits);

    const bool full = (out_size >= OUT_TOTAL);
    float* attn_out = full ? (out + OUT_ATTN) : nullptr;

    // one-time prep: tf32-round GEMM operands
    cvt_k<<<(BB*SS*HH/4 + 255)/256, 256>>>(enc, enc_t, BB*SS*HH/4);
    cvt_k<<<(HH*HH/4 + 255)/256, 256>>>(Ua, Ua_t, HH*HH/4);
    cvt_k<<<(HH*HH/4 + 255)/256, 256>>>(Wa, Wa_t, HH*HH/4);
    cvt_k<<<(VV*HH/4 + 255)/256, 256>>>(outW, outW_t, VV*HH/4);
    wcat_k<<<(4*HH*3*HH/4)/256, 256>>>(W_ih, W_hh);
    init_k<<<BB*HH/256, 256>>>(enc_h, enc_c);

    // keys_proj = enc @ Ua^T + bu
    gemm_tf32<<<dim3(HH/128, BB*SS/64), 256>>>(enc_t, HH, Ua_t, HH, bu, nullptr,
                                               keys, HH, HH);

    for (int t = 0; t < TT; t++) {
        // q = h @ Wa^T + ba  (h slice of xi)
        gemm_tf32<<<dim3(HH/128, 1), 256>>>(xi + 2*HH, 3*HH, Wa_t, HH, ba, nullptr,
                                            q, HH, HH);
        scores_k<<<BB*SS, 256>>>(Va, bv);
        ctx_fused_k<<<dim3(BB, 4), 256>>>(enc, emb, tgt, attn_out, t);
        // gates = [x|ctx|h] @ Wcat^T + b_ih + b_hh
        gemm_tf32<<<dim3(4*HH/128, 1), 256>>>(xi, 3*HH, Wcat, 3*HH, b_ih, b_hh,
                                              gates, 4*HH, 3*HH);
        lstm_ln_k<<<BB, 256>>>(ln_g, ln_b);
        // logits = nh @ outW^T + outb
        gemm_tf32<<<dim3(VV/128, 1), 256>>>(nh, HH, outW_t, HH, outb, nullptr,
                                            logits, VV, HH);
        logsoftmax_k<<<BB, 512>>>(out, t);
    }
    if (full) writehc_k<<<BB*HH/256, 256>>>(out);
}